// round 1
// baseline (speedup 1.0000x reference)
#include <cuda_runtime.h>
#include <cuda_bf16.h>

// out = X[M,256] * tril(W)[256,256]^T + b,  M = B*C = 262144
// Baseline: fp32 SGEMM, 128x128x16 tiles, triangular K-skip, fused bias.

#define TDIM 256      // T
#define BM 128
#define BN 128
#define BK 16

__global__ __launch_bounds__(256, 2)
void triu_sgemm(const float* __restrict__ X,
                const float* __restrict__ W,
                const float* __restrict__ bias,
                float* __restrict__ out)
{
    __shared__ float As[BK][BM];       // As[k][m]
    __shared__ float Bs[BK][BN];       // Bs[k][n] = masked W[n][k]

    const int m0 = blockIdx.x * BM;
    const int n0 = blockIdx.y * BN;
    const int tid = threadIdx.x;
    const int ty = tid >> 4;           // 0..15 -> row group
    const int tx = tid & 15;           // 0..15 -> col group

    // Triangular skip: columns in [n0, n0+BN) only need k < n0+BN
    const int kmax = (n0 + BN < TDIM) ? (n0 + BN) : TDIM;

    float acc[2][2][4][4];             // [rowhalf][colhalf][i][j]
    #pragma unroll
    for (int rh = 0; rh < 2; rh++)
        #pragma unroll
        for (int ch = 0; ch < 2; ch++)
            #pragma unroll
            for (int i = 0; i < 4; i++)
                #pragma unroll
                for (int j = 0; j < 4; j++)
                    acc[rh][ch][i][j] = 0.0f;

    for (int k0 = 0; k0 < kmax; k0 += BK) {
        // ---- stage A: 128 rows x 16 cols, float4, fully coalesced ----
        #pragma unroll
        for (int l = 0; l < 2; l++) {
            int idx = tid + l * 256;          // 0..511
            int row = idx >> 2;               // 0..127
            int c4  = idx & 3;                // 0..3
            float4 v = *reinterpret_cast<const float4*>(
                &X[(size_t)(m0 + row) * TDIM + k0 + c4 * 4]);
            As[c4 * 4 + 0][row] = v.x;
            As[c4 * 4 + 1][row] = v.y;
            As[c4 * 4 + 2][row] = v.z;
            As[c4 * 4 + 3][row] = v.w;
        }
        // ---- stage B: Bs[k][n] = (k<=n) ? W[n][k] : 0 ----
        #pragma unroll
        for (int l = 0; l < 8; l++) {
            int idx = tid + l * 256;          // 0..2047
            int k = idx >> 7;                 // 0..15
            int n = idx & 127;                // 0..127
            int gk = k0 + k, gn = n0 + n;
            Bs[k][n] = (gk <= gn) ? W[gn * TDIM + gk] : 0.0f;
        }
        __syncthreads();

        // ---- compute: 8x8 per thread as 2x2 float4 halves (bank-conflict-free) ----
        #pragma unroll
        for (int kk = 0; kk < BK; kk++) {
            float4 a0 = *reinterpret_cast<const float4*>(&As[kk][ty * 4]);
            float4 a1 = *reinterpret_cast<const float4*>(&As[kk][64 + ty * 4]);
            float4 b0 = *reinterpret_cast<const float4*>(&Bs[kk][tx * 4]);
            float4 b1 = *reinterpret_cast<const float4*>(&Bs[kk][64 + tx * 4]);
            const float ar[2][4] = {{a0.x, a0.y, a0.z, a0.w}, {a1.x, a1.y, a1.z, a1.w}};
            const float br[2][4] = {{b0.x, b0.y, b0.z, b0.w}, {b1.x, b1.y, b1.z, b1.w}};
            #pragma unroll
            for (int rh = 0; rh < 2; rh++)
                #pragma unroll
                for (int ch = 0; ch < 2; ch++)
                    #pragma unroll
                    for (int i = 0; i < 4; i++)
                        #pragma unroll
                        for (int j = 0; j < 4; j++)
                            acc[rh][ch][i][j] = fmaf(ar[rh][i], br[ch][j], acc[rh][ch][i][j]);
        }
        __syncthreads();
    }

    // ---- epilogue: add bias, float4 stores ----
    #pragma unroll
    for (int rh = 0; rh < 2; rh++) {
        #pragma unroll
        for (int i = 0; i < 4; i++) {
            int gm = m0 + rh * 64 + ty * 4 + i;
            #pragma unroll
            for (int ch = 0; ch < 2; ch++) {
                int gn = n0 + ch * 64 + tx * 4;
                float4 v;
                v.x = acc[rh][ch][i][0] + bias[gn + 0];
                v.y = acc[rh][ch][i][1] + bias[gn + 1];
                v.z = acc[rh][ch][i][2] + bias[gn + 2];
                v.w = acc[rh][ch][i][3] + bias[gn + 3];
                *reinterpret_cast<float4*>(&out[(size_t)gm * TDIM + gn]) = v;
            }
        }
    }
}

extern "C" void kernel_launch(void* const* d_in, const int* in_sizes, int n_in,
                              void* d_out, int out_size)
{
    const float* x = (const float*)d_in[0];   // (B, C, T) fp32, T contiguous
    const float* W = (const float*)d_in[1];   // (T, T)
    const float* b = (const float*)d_in[2];   // (T,)
    float* out = (float*)d_out;

    const int M = in_sizes[0] / TDIM;         // B*C = 262144
    dim3 grid(M / BM, TDIM / BN);             // (2048, 2)
    triu_sgemm<<<grid, 256>>>(x, W, b, out);
}

// round 3
// speedup vs baseline: 2.9344x; 2.9344x over previous
#include <cuda_runtime.h>
#include <cuda_bf16.h>
#include <cstdint>

// out[M,256] = X[M,256] * tril(W)^T + b  via mma.sync bf16 3-split:
//   out ~= Xh*Wh + Xl*Wh + Xh*Wl  (rel err ~1e-5)
// CTA tile 128x128, 8 warps (2x4), warp tile 64x32, K chunk 64, double-buffered.

#define TDIM 256
#define BM   128
#define BN   128
#define CK   64

// smem layout (bytes, per stage): Xh | Xl | Wh | Wl, each 128 rows x 128B
#define OXH 0
#define OXL 16384
#define OWH 32768
#define OWL 49152
#define STAGE 65536
#define SM_TOTAL (2 * STAGE)

__device__ __nv_bfloat16 g_Wh[TDIM * TDIM];
__device__ __nv_bfloat16 g_Wl[TDIM * TDIM];

__global__ void prep_w(const float* __restrict__ W) {
    int n = blockIdx.x, k = threadIdx.x;
    float v = (k <= n) ? W[n * TDIM + k] : 0.0f;
    __nv_bfloat16 h = __float2bfloat16_rn(v);
    __nv_bfloat16 l = __float2bfloat16_rn(v - __bfloat162float(h));
    g_Wh[n * TDIM + k] = h;
    g_Wl[n * TDIM + k] = l;
}

__device__ __forceinline__ uint32_t smem_u32(const void* p) {
    uint32_t a;
    asm("{ .reg .u64 t; cvta.to.shared.u64 t, %1; cvt.u32.u64 %0, t; }" : "=r"(a) : "l"(p));
    return a;
}
__device__ __forceinline__ uint32_t swz(uint32_t o) { return o ^ ((o >> 3) & 0x70); }

#define CP16(dst, src) \
    asm volatile("cp.async.cg.shared.global [%0], [%1], 16;" :: "r"(dst), "l"(src) : "memory")
#define CP_COMMIT() asm volatile("cp.async.commit_group;" ::: "memory")
#define CP_WAIT0()  asm volatile("cp.async.wait_group 0;" ::: "memory")

__device__ __forceinline__ void ldsm4(uint32_t (&r)[4], uint32_t a) {
    asm volatile("ldmatrix.sync.aligned.m8n8.x4.shared.b16 {%0,%1,%2,%3}, [%4];"
        : "=r"(r[0]), "=r"(r[1]), "=r"(r[2]), "=r"(r[3]) : "r"(a));
}
__device__ __forceinline__ void mma16816(float (&d)[4], const uint32_t (&a)[4],
                                         const uint32_t* b) {
    asm volatile("mma.sync.aligned.m16n8k16.row.col.f32.bf16.bf16.f32 "
        "{%0,%1,%2,%3}, {%4,%5,%6,%7}, {%8,%9}, {%0,%1,%2,%3};"
        : "+f"(d[0]), "+f"(d[1]), "+f"(d[2]), "+f"(d[3])
        : "r"(a[0]), "r"(a[1]), "r"(a[2]), "r"(a[3]), "r"(b[0]), "r"(b[1]));
}
__device__ __forceinline__ uint32_t pack2(__nv_bfloat16 a, __nv_bfloat16 b) {
    __nv_bfloat162 t = __halves2bfloat162(a, b);
    return *reinterpret_cast<uint32_t*>(&t);
}

__global__ __launch_bounds__(256)
void triu_hmma(const float* __restrict__ X, const float* __restrict__ bias,
               float* __restrict__ out)
{
    extern __shared__ char smem[];
    const uint32_t sb = smem_u32(smem);
    const int tid = threadIdx.x;
    const int wid = tid >> 5, lane = tid & 31;
    const size_t m0 = (size_t)blockIdx.x * BM;
    const int n0 = blockIdx.y * BN;
    const int nch = (n0 + BN) / CK;                 // triangular K-skip: 2 or 4

    const int rw = wid >> 2;                        // warp row group (0..1)
    const int cw = wid & 3;                         // warp col group (0..3)

    float acc[4][4][4];
    #pragma unroll
    for (int i = 0; i < 4; i++)
        #pragma unroll
        for (int j = 0; j < 4; j++)
            #pragma unroll
            for (int e = 0; e < 4; e++) acc[i][j][e] = 0.0f;

    // per-thread staging coords
    const int xrow = tid >> 4, xq = tid & 15;        // X: 16 float4 per 64-float row
    const int wrow = tid >> 3, wq = tid & 7;         // W: 8 x 16B per 128B row

    float4 xv[8];

    // ---- prologue: stage chunk 0 ----
    {
        const int k0 = 0;
        #pragma unroll
        for (int i = 0; i < 4; i++) {
            int r = wrow + i * 32;
            uint32_t so = swz((uint32_t)(r * 128 + wq * 16));
            CP16(sb + OWH + so, &g_Wh[(n0 + r) * TDIM + k0 + wq * 8]);
            CP16(sb + OWL + so, &g_Wl[(n0 + r) * TDIM + k0 + wq * 8]);
        }
        CP_COMMIT();
        #pragma unroll
        for (int i = 0; i < 8; i++) {
            int r = xrow + i * 16;
            xv[i] = *reinterpret_cast<const float4*>(&X[(m0 + r) * TDIM + k0 + xq * 4]);
        }
        #pragma unroll
        for (int i = 0; i < 8; i++) {
            int r = xrow + i * 16;
            float4 v = xv[i];
            __nv_bfloat16 h0 = __float2bfloat16_rn(v.x), h1 = __float2bfloat16_rn(v.y);
            __nv_bfloat16 h2 = __float2bfloat16_rn(v.z), h3 = __float2bfloat16_rn(v.w);
            uint2 hp = make_uint2(pack2(h0, h1), pack2(h2, h3));
            uint2 lp = make_uint2(
                pack2(__float2bfloat16_rn(v.x - __bfloat162float(h0)),
                      __float2bfloat16_rn(v.y - __bfloat162float(h1))),
                pack2(__float2bfloat16_rn(v.z - __bfloat162float(h2)),
                      __float2bfloat16_rn(v.w - __bfloat162float(h3))));
            uint32_t so = swz((uint32_t)(r * 128 + xq * 8));
            *reinterpret_cast<uint2*>(smem + OXH + so) = hp;
            *reinterpret_cast<uint2*>(smem + OXL + so) = lp;
        }
        CP_WAIT0();
        __syncthreads();
    }

    int st = 0;
    for (int c = 0; c < nch; c++) {
        const uint32_t bs = sb + st * STAGE;
        const int nxt = c + 1;

        if (nxt < nch) {
            const int k0 = nxt * CK;
            const uint32_t ns = sb + (st ^ 1) * STAGE;
            #pragma unroll
            for (int i = 0; i < 4; i++) {
                int r = wrow + i * 32;
                uint32_t so = swz((uint32_t)(r * 128 + wq * 16));
                CP16(ns + OWH + so, &g_Wh[(n0 + r) * TDIM + k0 + wq * 8]);
                CP16(ns + OWL + so, &g_Wl[(n0 + r) * TDIM + k0 + wq * 8]);
            }
            CP_COMMIT();
            #pragma unroll
            for (int i = 0; i < 8; i++) {
                int r = xrow + i * 16;
                xv[i] = *reinterpret_cast<const float4*>(&X[(m0 + r) * TDIM + k0 + xq * 4]);
            }
        }

        // ---- compute chunk c (4 k-steps of 16) ----
        #pragma unroll
        for (int kk = 0; kk < 4; kk++) {
            uint32_t ah[4][4], al[4][4], bh[4][2], bl[4][2];
            const uint32_t abyte = (uint32_t)(kk * 32 + ((lane >> 4) << 4));
            #pragma unroll
            for (int i = 0; i < 4; i++) {
                int ar = rw * 64 + i * 16 + (lane & 15);
                uint32_t so = swz((uint32_t)(ar * 128) + abyte);
                ldsm4(ah[i], bs + OXH + so);
                ldsm4(al[i], bs + OXL + so);
            }
            const int g = lane >> 3;
            const uint32_t bbyte = (uint32_t)(kk * 32 + ((g & 1) << 4));
            #pragma unroll
            for (int j2 = 0; j2 < 2; j2++) {
                int br = cw * 32 + j2 * 16 + ((g >> 1) << 3) + (lane & 7);
                uint32_t so = swz((uint32_t)(br * 128) + bbyte);
                uint32_t r[4];
                ldsm4(r, bs + OWH + so);
                bh[2 * j2][0] = r[0]; bh[2 * j2][1] = r[1];
                bh[2 * j2 + 1][0] = r[2]; bh[2 * j2 + 1][1] = r[3];
                ldsm4(r, bs + OWL + so);
                bl[2 * j2][0] = r[0]; bl[2 * j2][1] = r[1];
                bl[2 * j2 + 1][0] = r[2]; bl[2 * j2 + 1][1] = r[3];
            }
            #pragma unroll
            for (int i = 0; i < 4; i++)
                #pragma unroll
                for (int j = 0; j < 4; j++) {
                    mma16816(acc[i][j], ah[i], bh[j]);
                    mma16816(acc[i][j], al[i], bh[j]);
                    mma16816(acc[i][j], ah[i], bl[j]);
                }
        }

        if (nxt < nch) {
            const uint32_t ns = sb - sb;  // offset form below uses smem ptr
            (void)ns;
            char* nb = smem + (st ^ 1) * STAGE;
            #pragma unroll
            for (int i = 0; i < 8; i++) {
                int r = xrow + i * 16;
                float4 v = xv[i];
                __nv_bfloat16 h0 = __float2bfloat16_rn(v.x), h1 = __float2bfloat16_rn(v.y);
                __nv_bfloat16 h2 = __float2bfloat16_rn(v.z), h3 = __float2bfloat16_rn(v.w);
                uint2 hp = make_uint2(pack2(h0, h1), pack2(h2, h3));
                uint2 lp = make_uint2(
                    pack2(__float2bfloat16_rn(v.x - __bfloat162float(h0)),
                          __float2bfloat16_rn(v.y - __bfloat162float(h1))),
                    pack2(__float2bfloat16_rn(v.z - __bfloat162float(h2)),
                          __float2bfloat16_rn(v.w - __bfloat162float(h3))));
                uint32_t so = swz((uint32_t)(r * 128 + xq * 8));
                *reinterpret_cast<uint2*>(nb + OXH + so) = hp;
                *reinterpret_cast<uint2*>(nb + OXL + so) = lp;
            }
        }
        CP_WAIT0();
        __syncthreads();
        st ^= 1;
    }

    // ---- epilogue: bias + direct stores (32B sectors fully used) ----
    const int ncol0 = n0 + cw * 32 + 2 * (lane & 3);
    float2 bj[4];
    #pragma unroll
    for (int j = 0; j < 4; j++)
        bj[j] = *reinterpret_cast<const float2*>(&bias[ncol0 + j * 8]);

    const size_t mrow = m0 + rw * 64 + (lane >> 2);
    #pragma unroll
    for (int i = 0; i < 4; i++) {
        size_t r0 = mrow + i * 16, r1 = r0 + 8;
        #pragma unroll
        for (int j = 0; j < 4; j++) {
            float2 v0 = make_float2(acc[i][j][0] + bj[j].x, acc[i][j][1] + bj[j].y);
            float2 v1 = make_float2(acc[i][j][2] + bj[j].x, acc[i][j][3] + bj[j].y);
            *reinterpret_cast<float2*>(&out[r0 * TDIM + ncol0 + j * 8]) = v0;
            *reinterpret_cast<float2*>(&out[r1 * TDIM + ncol0 + j * 8]) = v1;
        }
    }
}

extern "C" void kernel_launch(void* const* d_in, const int* in_sizes, int n_in,
                              void* d_out, int out_size)
{
    const float* x = (const float*)d_in[0];
    const float* W = (const float*)d_in[1];
    const float* b = (const float*)d_in[2];
    float* out = (float*)d_out;

    prep_w<<<TDIM, TDIM>>>(W);

    cudaFuncSetAttribute(triu_hmma, cudaFuncAttributeMaxDynamicSharedMemorySize, SM_TOTAL);
    const int M = in_sizes[0] / TDIM;               // 262144
    dim3 grid(M / BM, TDIM / BN);                   // (2048, 2)
    triu_hmma<<<grid, 256, SM_TOTAL>>>(x, b, out);
}

// round 4
// speedup vs baseline: 4.4833x; 1.5278x over previous
#include <cuda_runtime.h>
#include <cuda_fp16.h>
#include <cstdint>

// out[M,256] = X[M,256] * tril(W)^T + b  via mma.sync fp16 2-split:
//   out ~= Xh*Wh + Xl*Wh,  Wh = fp16(W), Xh = fp16(x), Xl = fp16(x - Xh)
//   (dropped X*(W-Wh) term ~2.8e-4 rms rel err; threshold 1e-3)
// CTA tile 128x64, 8 warps (4x2), warp tile 32x32, K chunk 64, double-buffered,
// triangular K-skip per N-block (1..4 chunks), 2 CTAs/SM.

#define TDIM 256
#define BM   128
#define BN   64
#define CK   64

// smem per stage: Xh[128][64]f16 | Xl[128][64]f16 | Wh[64][64]f16 (128B rows, SW128)
#define OXH 0
#define OXL 16384
#define OWH 32768
#define STAGE 40960
#define SM_TOTAL (2 * STAGE)

__device__ __half g_Wh[TDIM * TDIM];

__global__ void prep_w(const float* __restrict__ W) {
    int n = blockIdx.x, k = threadIdx.x;
    float v = (k <= n) ? W[n * TDIM + k] : 0.0f;
    g_Wh[n * TDIM + k] = __float2half_rn(v);
}

__device__ __forceinline__ uint32_t smem_u32(const void* p) {
    uint32_t a;
    asm("{ .reg .u64 t; cvta.to.shared.u64 t, %1; cvt.u32.u64 %0, t; }" : "=r"(a) : "l"(p));
    return a;
}
__device__ __forceinline__ uint32_t swz(uint32_t o) { return o ^ ((o >> 3) & 0x70); }

#define CP16(dst, src) \
    asm volatile("cp.async.cg.shared.global [%0], [%1], 16;" :: "r"(dst), "l"(src) : "memory")
#define CP_COMMIT() asm volatile("cp.async.commit_group;" ::: "memory")
#define CP_WAIT0()  asm volatile("cp.async.wait_group 0;" ::: "memory")

__device__ __forceinline__ void ldsm4(uint32_t (&r)[4], uint32_t a) {
    asm volatile("ldmatrix.sync.aligned.m8n8.x4.shared.b16 {%0,%1,%2,%3}, [%4];"
        : "=r"(r[0]), "=r"(r[1]), "=r"(r[2]), "=r"(r[3]) : "r"(a));
}
__device__ __forceinline__ void mma16816(float (&d)[4], const uint32_t (&a)[4],
                                         const uint32_t* b) {
    asm volatile("mma.sync.aligned.m16n8k16.row.col.f32.f16.f16.f32 "
        "{%0,%1,%2,%3}, {%4,%5,%6,%7}, {%8,%9}, {%0,%1,%2,%3};"
        : "+f"(d[0]), "+f"(d[1]), "+f"(d[2]), "+f"(d[3])
        : "r"(a[0]), "r"(a[1]), "r"(a[2]), "r"(a[3]), "r"(b[0]), "r"(b[1]));
}
__device__ __forceinline__ uint32_t pack2(__half a, __half b) {
    __half2 t = __halves2half2(a, b);
    return *reinterpret_cast<uint32_t*>(&t);
}

__device__ __forceinline__ void cvt_store(char* base, int row, int q, float4 v) {
    __half h0 = __float2half_rn(v.x), h1 = __float2half_rn(v.y);
    __half h2 = __float2half_rn(v.z), h3 = __float2half_rn(v.w);
    uint2 hp = make_uint2(pack2(h0, h1), pack2(h2, h3));
    uint2 lp = make_uint2(
        pack2(__float2half_rn(v.x - __half2float(h0)),
              __float2half_rn(v.y - __half2float(h1))),
        pack2(__float2half_rn(v.z - __half2float(h2)),
              __float2half_rn(v.w - __half2float(h3))));
    uint32_t so = swz((uint32_t)(row * 128 + q * 8));
    *reinterpret_cast<uint2*>(base + OXH + so) = hp;
    *reinterpret_cast<uint2*>(base + OXL + so) = lp;
}

__global__ __launch_bounds__(256, 2)
void triu_hmma2(const float* __restrict__ X, const float* __restrict__ bias,
                float* __restrict__ out)
{
    extern __shared__ char smem[];
    const uint32_t sb = smem_u32(smem);
    const int tid = threadIdx.x;
    const int wid = tid >> 5, lane = tid & 31;

    // interleave N-blocks across adjacent CTAs for L2 X-chunk reuse + balance
    const int bid = blockIdx.x;
    const int nb = bid & 3;                          // n-block 0..3
    const size_t m0 = (size_t)(bid >> 2) * BM;
    const int n0 = nb * BN;
    const int nch = nb + 1;                          // triangular: 1..4 chunks

    const int rw = wid >> 1;                         // warp row group 0..3
    const int cw = wid & 1;                          // warp col group 0..1

    float acc[2][4][4];
    #pragma unroll
    for (int i = 0; i < 2; i++)
        #pragma unroll
        for (int j = 0; j < 4; j++)
            #pragma unroll
            for (int e = 0; e < 4; e++) acc[i][j][e] = 0.0f;

    const int xrow = tid >> 4, xq = tid & 15;        // X: 16 float4 per 64-col row
    float4 xv[8];

    // ---- prologue: stage chunk 0 ----
    {
        #pragma unroll
        for (int i = 0; i < 2; i++) {
            int idx = tid + i * 256;                 // 0..511
            int r = idx >> 3, q = idx & 7;           // 64 rows x 8 x 16B
            uint32_t so = swz((uint32_t)(r * 128 + q * 16));
            CP16(sb + OWH + so, &g_Wh[(n0 + r) * TDIM + q * 8]);
        }
        CP_COMMIT();
        #pragma unroll
        for (int i = 0; i < 8; i++) {
            int r = xrow + i * 16;
            xv[i] = *reinterpret_cast<const float4*>(&X[(m0 + r) * TDIM + xq * 4]);
        }
        #pragma unroll
        for (int i = 0; i < 8; i++) cvt_store(smem, xrow + i * 16, xq, xv[i]);
        CP_WAIT0();
        __syncthreads();
    }

    int st = 0;
    for (int c = 0; c < nch; c++) {
        const uint32_t bs = sb + st * STAGE;
        const bool more = (c + 1 < nch);

        if (more) {
            const int k0 = (c + 1) * CK;
            const uint32_t ns = sb + (st ^ 1) * STAGE;
            #pragma unroll
            for (int i = 0; i < 2; i++) {
                int idx = tid + i * 256;
                int r = idx >> 3, q = idx & 7;
                uint32_t so = swz((uint32_t)(r * 128 + q * 16));
                CP16(ns + OWH + so, &g_Wh[(n0 + r) * TDIM + k0 + q * 8]);
            }
            CP_COMMIT();
            #pragma unroll
            for (int i = 0; i < 8; i++) {
                int r = xrow + i * 16;
                xv[i] = *reinterpret_cast<const float4*>(&X[(m0 + r) * TDIM + k0 + xq * 4]);
            }
        }

        // ---- compute chunk c: 4 k-steps of 16 ----
        #pragma unroll
        for (int kk = 0; kk < 4; kk++) {
            uint32_t ah[2][4], al[2][4], bh[4][2];
            const uint32_t abyte = (uint32_t)(kk * 32 + ((lane >> 4) << 4));
            #pragma unroll
            for (int i = 0; i < 2; i++) {
                int ar = rw * 32 + i * 16 + (lane & 15);
                uint32_t so = swz((uint32_t)(ar * 128) + abyte);
                ldsm4(ah[i], bs + OXH + so);
                ldsm4(al[i], bs + OXL + so);
            }
            const int g = lane >> 3;
            const uint32_t bbyte = (uint32_t)(kk * 32 + ((g & 1) << 4));
            #pragma unroll
            for (int j2 = 0; j2 < 2; j2++) {
                int br = cw * 32 + j2 * 16 + ((g >> 1) << 3) + (lane & 7);
                uint32_t so = swz((uint32_t)(br * 128) + bbyte);
                uint32_t r[4];
                ldsm4(r, bs + OWH + so);
                bh[2 * j2][0] = r[0]; bh[2 * j2][1] = r[1];
                bh[2 * j2 + 1][0] = r[2]; bh[2 * j2 + 1][1] = r[3];
            }
            #pragma unroll
            for (int i = 0; i < 2; i++)
                #pragma unroll
                for (int j = 0; j < 4; j++) {
                    mma16816(acc[i][j], ah[i], bh[j]);
                    mma16816(acc[i][j], al[i], bh[j]);
                }
        }

        if (more) {
            char* nbuf = smem + (st ^ 1) * STAGE;
            #pragma unroll
            for (int i = 0; i < 8; i++) cvt_store(nbuf, xrow + i * 16, xq, xv[i]);
        }
        CP_WAIT0();
        __syncthreads();
        st ^= 1;
    }

    // ---- epilogue: bias + direct coalesced stores ----
    const int ncol0 = n0 + cw * 32 + 2 * (lane & 3);
    float2 bj[4];
    #pragma unroll
    for (int j = 0; j < 4; j++)
        bj[j] = *reinterpret_cast<const float2*>(&bias[ncol0 + j * 8]);

    const size_t mrow = m0 + rw * 32 + (lane >> 2);
    #pragma unroll
    for (int i = 0; i < 2; i++) {
        size_t r0 = mrow + i * 16, r1 = r0 + 8;
        #pragma unroll
        for (int j = 0; j < 4; j++) {
            float2 v0 = make_float2(acc[i][j][0] + bj[j].x, acc[i][j][1] + bj[j].y);
            float2 v1 = make_float2(acc[i][j][2] + bj[j].x, acc[i][j][3] + bj[j].y);
            *reinterpret_cast<float2*>(&out[r0 * TDIM + ncol0 + j * 8]) = v0;
            *reinterpret_cast<float2*>(&out[r1 * TDIM + ncol0 + j * 8]) = v1;
        }
    }
}

extern "C" void kernel_launch(void* const* d_in, const int* in_sizes, int n_in,
                              void* d_out, int out_size)
{
    const float* x = (const float*)d_in[0];
    const float* W = (const float*)d_in[1];
    const float* b = (const float*)d_in[2];
    float* out = (float*)d_out;

    prep_w<<<TDIM, TDIM>>>(W);

    cudaFuncSetAttribute(triu_hmma2, cudaFuncAttributeMaxDynamicSharedMemorySize, SM_TOTAL);
    const int M = in_sizes[0] / TDIM;               // 262144
    const int nblocks = (M / BM) * (TDIM / BN);     // 8192
    triu_hmma2<<<nblocks, 256, SM_TOTAL>>>(x, b, out);
}

// round 5
// speedup vs baseline: 4.8813x; 1.0888x over previous
#include <cuda_runtime.h>
#include <cuda_fp16.h>
#include <cstdint>

// out[M,256] = X[M,256] * tril(W)^T + b  via single fp16 mma.sync:
//   out ~= fp16(X) * fp16(tril(W))^T + b   (rel err ~3e-4 vs 1e-3 threshold)
// CTA tile 128x64, 8 warps (4x2), warp tile 32x32, K chunk 64, double-buffered,
// triangular K-skip per N-block (1..4 chunks), 3 CTAs/SM.

#define TDIM 256
#define BM   128
#define BN   64
#define CK   64

// smem per stage: Xh[128][64]f16 (SW128) | Wh[64][64]f16 (SW128)
#define OXH 0
#define OWH 16384
#define STAGE 24576
#define SM_TOTAL (2 * STAGE)

__device__ __half g_Wh[TDIM * TDIM];

__global__ void prep_w(const float* __restrict__ W) {
    int n = blockIdx.x, k = threadIdx.x;
    float v = (k <= n) ? W[n * TDIM + k] : 0.0f;
    g_Wh[n * TDIM + k] = __float2half_rn(v);
}

__device__ __forceinline__ uint32_t smem_u32(const void* p) {
    uint32_t a;
    asm("{ .reg .u64 t; cvta.to.shared.u64 t, %1; cvt.u32.u64 %0, t; }" : "=r"(a) : "l"(p));
    return a;
}
__device__ __forceinline__ uint32_t swz(uint32_t o) { return o ^ ((o >> 3) & 0x70); }

#define CP16(dst, src) \
    asm volatile("cp.async.cg.shared.global [%0], [%1], 16;" :: "r"(dst), "l"(src) : "memory")
#define CP_COMMIT() asm volatile("cp.async.commit_group;" ::: "memory")
#define CP_WAIT0()  asm volatile("cp.async.wait_group 0;" ::: "memory")

__device__ __forceinline__ void ldsm4(uint32_t (&r)[4], uint32_t a) {
    asm volatile("ldmatrix.sync.aligned.m8n8.x4.shared.b16 {%0,%1,%2,%3}, [%4];"
        : "=r"(r[0]), "=r"(r[1]), "=r"(r[2]), "=r"(r[3]) : "r"(a));
}
__device__ __forceinline__ void mma16816(float (&d)[4], const uint32_t (&a)[4],
                                         const uint32_t* b) {
    asm volatile("mma.sync.aligned.m16n8k16.row.col.f32.f16.f16.f32 "
        "{%0,%1,%2,%3}, {%4,%5,%6,%7}, {%8,%9}, {%0,%1,%2,%3};"
        : "+f"(d[0]), "+f"(d[1]), "+f"(d[2]), "+f"(d[3])
        : "r"(a[0]), "r"(a[1]), "r"(a[2]), "r"(a[3]), "r"(b[0]), "r"(b[1]));
}
__device__ __forceinline__ uint32_t pack2(__half a, __half b) {
    __half2 t = __halves2half2(a, b);
    return *reinterpret_cast<uint32_t*>(&t);
}

__device__ __forceinline__ void cvt_store(char* base, int row, int q, float4 v) {
    uint2 hp = make_uint2(pack2(__float2half_rn(v.x), __float2half_rn(v.y)),
                          pack2(__float2half_rn(v.z), __float2half_rn(v.w)));
    uint32_t so = swz((uint32_t)(row * 128 + q * 8));
    *reinterpret_cast<uint2*>(base + OXH + so) = hp;
}

__global__ __launch_bounds__(256, 3)
void triu_hmma1(const float* __restrict__ X, const float* __restrict__ bias,
                float* __restrict__ out)
{
    extern __shared__ char smem[];
    const uint32_t sb = smem_u32(smem);
    const int tid = threadIdx.x;
    const int wid = tid >> 5, lane = tid & 31;

    // interleave N-blocks across adjacent CTAs for L2 X-chunk reuse + balance
    const int bid = blockIdx.x;
    const int nb = bid & 3;                          // n-block 0..3
    const size_t m0 = (size_t)(bid >> 2) * BM;
    const int n0 = nb * BN;
    const int nch = nb + 1;                          // triangular: 1..4 chunks

    const int rw = wid >> 1;                         // warp row group 0..3
    const int cw = wid & 1;                          // warp col group 0..1

    float acc[2][4][4];
    #pragma unroll
    for (int i = 0; i < 2; i++)
        #pragma unroll
        for (int j = 0; j < 4; j++)
            #pragma unroll
            for (int e = 0; e < 4; e++) acc[i][j][e] = 0.0f;

    const int xrow = tid >> 4, xq = tid & 15;        // X: 16 float4 per 64-col row
    float4 xv[8];

    // ---- prologue: stage chunk 0 ----
    {
        #pragma unroll
        for (int i = 0; i < 2; i++) {
            int idx = tid + i * 256;                 // 0..511
            int r = idx >> 3, q = idx & 7;           // 64 rows x 8 x 16B
            uint32_t so = swz((uint32_t)(r * 128 + q * 16));
            CP16(sb + OWH + so, &g_Wh[(n0 + r) * TDIM + q * 8]);
        }
        CP_COMMIT();
        #pragma unroll
        for (int i = 0; i < 8; i++) {
            int r = xrow + i * 16;
            xv[i] = *reinterpret_cast<const float4*>(&X[(m0 + r) * TDIM + xq * 4]);
        }
        #pragma unroll
        for (int i = 0; i < 8; i++) cvt_store(smem, xrow + i * 16, xq, xv[i]);
        CP_WAIT0();
        __syncthreads();
    }

    int st = 0;
    for (int c = 0; c < nch; c++) {
        const uint32_t bs = sb + st * STAGE;
        const bool more = (c + 1 < nch);

        if (more) {
            const int k0 = (c + 1) * CK;
            const uint32_t ns = sb + (st ^ 1) * STAGE;
            #pragma unroll
            for (int i = 0; i < 2; i++) {
                int idx = tid + i * 256;
                int r = idx >> 3, q = idx & 7;
                uint32_t so = swz((uint32_t)(r * 128 + q * 16));
                CP16(ns + OWH + so, &g_Wh[(n0 + r) * TDIM + k0 + q * 8]);
            }
            CP_COMMIT();
            #pragma unroll
            for (int i = 0; i < 8; i++) {
                int r = xrow + i * 16;
                xv[i] = *reinterpret_cast<const float4*>(&X[(m0 + r) * TDIM + k0 + xq * 4]);
            }
        }

        // ---- compute chunk c: 4 k-steps of 16 ----
        #pragma unroll
        for (int kk = 0; kk < 4; kk++) {
            uint32_t ah[2][4], bh[4][2];
            const uint32_t abyte = (uint32_t)(kk * 32 + ((lane >> 4) << 4));
            #pragma unroll
            for (int i = 0; i < 2; i++) {
                int ar = rw * 32 + i * 16 + (lane & 15);
                uint32_t so = swz((uint32_t)(ar * 128) + abyte);
                ldsm4(ah[i], bs + OXH + so);
            }
            const int g = lane >> 3;
            const uint32_t bbyte = (uint32_t)(kk * 32 + ((g & 1) << 4));
            #pragma unroll
            for (int j2 = 0; j2 < 2; j2++) {
                int br = cw * 32 + j2 * 16 + ((g >> 1) << 3) + (lane & 7);
                uint32_t so = swz((uint32_t)(br * 128) + bbyte);
                uint32_t r[4];
                ldsm4(r, bs + OWH + so);
                bh[2 * j2][0] = r[0]; bh[2 * j2][1] = r[1];
                bh[2 * j2 + 1][0] = r[2]; bh[2 * j2 + 1][1] = r[3];
            }
            #pragma unroll
            for (int i = 0; i < 2; i++)
                #pragma unroll
                for (int j = 0; j < 4; j++)
                    mma16816(acc[i][j], ah[i], bh[j]);
        }

        if (more) {
            char* nbuf = smem + (st ^ 1) * STAGE;
            #pragma unroll
            for (int i = 0; i < 8; i++) cvt_store(nbuf, xrow + i * 16, xq, xv[i]);
        }
        CP_WAIT0();
        __syncthreads();
        st ^= 1;
    }

    // ---- epilogue: bias + direct coalesced stores ----
    const int ncol0 = n0 + cw * 32 + 2 * (lane & 3);
    float2 bj[4];
    #pragma unroll
    for (int j = 0; j < 4; j++)
        bj[j] = *reinterpret_cast<const float2*>(&bias[ncol0 + j * 8]);

    const size_t mrow = m0 + rw * 32 + (lane >> 2);
    #pragma unroll
    for (int i = 0; i < 2; i++) {
        size_t r0 = mrow + i * 16, r1 = r0 + 8;
        #pragma unroll
        for (int j = 0; j < 4; j++) {
            float2 v0 = make_float2(acc[i][j][0] + bj[j].x, acc[i][j][1] + bj[j].y);
            float2 v1 = make_float2(acc[i][j][2] + bj[j].x, acc[i][j][3] + bj[j].y);
            *reinterpret_cast<float2*>(&out[r0 * TDIM + ncol0 + j * 8]) = v0;
            *reinterpret_cast<float2*>(&out[r1 * TDIM + ncol0 + j * 8]) = v1;
        }
    }
}

extern "C" void kernel_launch(void* const* d_in, const int* in_sizes, int n_in,
                              void* d_out, int out_size)
{
    const float* x = (const float*)d_in[0];
    const float* W = (const float*)d_in[1];
    const float* b = (const float*)d_in[2];
    float* out = (float*)d_out;

    prep_w<<<TDIM, TDIM>>>(W);

    cudaFuncSetAttribute(triu_hmma1, cudaFuncAttributeMaxDynamicSharedMemorySize, SM_TOTAL);
    const int M = in_sizes[0] / TDIM;               // 262144
    const int nblocks = (M / BM) * (TDIM / BN);     // 8192
    triu_hmma1<<<nblocks, 256, SM_TOTAL>>>(x, b, out);
}

// round 6
// speedup vs baseline: 4.9885x; 1.0220x over previous
#include <cuda_runtime.h>
#include <cuda_fp16.h>
#include <cstdint>

// out[M,256] = X[M,256] * tril(W)^T + b  via single fp16 mma.sync.
// CTA tile 128x64, 4 warps (2x2), warp tile 64x32, K chunk 32, double-buffered X,
// W fully preloaded to smem once per CTA, triangular K-skip (2/4/6/8 chunks),
// 3 CTAs/SM.

#define TDIM 256
#define BM   128
#define BN   64
#define CK   32
#define NTHREADS 128

// smem: W[64][512B] swizzled | X stage0 8KB | X stage1 8KB
#define OW   0
#define OX0  32768
#define OX1  40960
#define SM_TOTAL 49152

__device__ __half g_Wh[TDIM * TDIM];

__global__ void prep_w(const float* __restrict__ W) {
    int n = blockIdx.x, k = threadIdx.x;
    float v = (k <= n) ? W[n * TDIM + k] : 0.0f;
    g_Wh[n * TDIM + k] = __float2half_rn(v);
}

__device__ __forceinline__ uint32_t smem_u32(const void* p) {
    uint32_t a;
    asm("{ .reg .u64 t; cvta.to.shared.u64 t, %1; cvt.u32.u64 %0, t; }" : "=r"(a) : "l"(p));
    return a;
}

// W layout: row n = 512B (256 fp16 K-cols), 16B chunk c swizzled by n&7 -> conflict-free
__device__ __forceinline__ uint32_t woff(int n, int c) {
    return (uint32_t)(n * 512 + ((c ^ (n & 7)) << 4));
}
// X layout: paired rows, two 64B (32 fp16) rows per 128B smem row; chunkin in 0..7
__device__ __forceinline__ uint32_t xoff(int row, int chunkin) {
    return (uint32_t)((row >> 1) * 128 + ((chunkin ^ ((row >> 1) & 7)) << 4));
}

#define CP16(dst, src) \
    asm volatile("cp.async.cg.shared.global [%0], [%1], 16;" :: "r"(dst), "l"(src) : "memory")
#define CP_COMMIT() asm volatile("cp.async.commit_group;" ::: "memory")
#define CP_WAIT0()  asm volatile("cp.async.wait_group 0;" ::: "memory")

__device__ __forceinline__ void ldsm4(uint32_t (&r)[4], uint32_t a) {
    asm volatile("ldmatrix.sync.aligned.m8n8.x4.shared.b16 {%0,%1,%2,%3}, [%4];"
        : "=r"(r[0]), "=r"(r[1]), "=r"(r[2]), "=r"(r[3]) : "r"(a));
}
__device__ __forceinline__ void mma16816(float (&d)[4], const uint32_t (&a)[4],
                                         const uint32_t* b) {
    asm volatile("mma.sync.aligned.m16n8k16.row.col.f32.f16.f16.f32 "
        "{%0,%1,%2,%3}, {%4,%5,%6,%7}, {%8,%9}, {%0,%1,%2,%3};"
        : "+f"(d[0]), "+f"(d[1]), "+f"(d[2]), "+f"(d[3])
        : "r"(a[0]), "r"(a[1]), "r"(a[2]), "r"(a[3]), "r"(b[0]), "r"(b[1]));
}
__device__ __forceinline__ uint32_t pack2(float a, float b) {
    __half2 t = __halves2half2(__float2half_rn(a), __float2half_rn(b));
    return *reinterpret_cast<uint32_t*>(&t);
}

__global__ __launch_bounds__(NTHREADS, 3)
void triu_v6(const float* __restrict__ X, const float* __restrict__ bias,
             float* __restrict__ out)
{
    extern __shared__ char smem[];
    const uint32_t sb = smem_u32(smem);
    const int tid = threadIdx.x;
    const int wid = tid >> 5, lane = tid & 31;

    const int bid = blockIdx.x;
    const int nb = bid & 3;                           // n-block 0..3
    const size_t m0 = (size_t)(bid >> 2) * BM;
    const int n0 = nb * BN;
    const int nch = 2 * (nb + 1);                     // CK=32 chunks: 2,4,6,8

    const int rw = wid >> 1;                          // 0..1 (64 rows each)
    const int cw = wid & 1;                           // 0..1 (32 cols each)

    // ---- prologue: preload ALL needed W (64 rows x nch*32 k-cols) via cp.async ----
    const int wchunks = 4 * nch;                      // 16B chunks per row (<=32)
    #pragma unroll
    for (int i = 0; i < 16; i++) {
        int s = tid + i * NTHREADS;                   // 0..2047
        int n = s >> 5, c = s & 31;
        if (c < wchunks)
            CP16(sb + OW + woff(n, c), &g_Wh[(n0 + n) * TDIM + c * 8]);
    }
    CP_COMMIT();

    // ---- stage X chunk 0 ----
    float4 xv[8];
    #pragma unroll
    for (int i = 0; i < 4; i++) {
        int s = tid + i * NTHREADS;                   // 0..511
        int row = s >> 2, cc = s & 3;
        const float* p = &X[(m0 + row) * TDIM + cc * 8];
        xv[2 * i]     = *reinterpret_cast<const float4*>(p);
        xv[2 * i + 1] = *reinterpret_cast<const float4*>(p + 4);
    }
    #pragma unroll
    for (int i = 0; i < 4; i++) {
        int s = tid + i * NTHREADS;
        int row = s >> 2, cc = s & 3;
        float4 a = xv[2 * i], b = xv[2 * i + 1];
        uint4 h = make_uint4(pack2(a.x, a.y), pack2(a.z, a.w),
                             pack2(b.x, b.y), pack2(b.z, b.w));
        int chunkin = ((row & 1) << 2) | cc;
        *reinterpret_cast<uint4*>(smem + OX0 + xoff(row, chunkin)) = h;
    }
    CP_WAIT0();
    __syncthreads();

    float acc[4][4][4];
    #pragma unroll
    for (int i = 0; i < 4; i++)
        #pragma unroll
        for (int j = 0; j < 4; j++)
            #pragma unroll
            for (int e = 0; e < 4; e++) acc[i][j][e] = 0.0f;

    int st = 0;
    for (int c = 0; c < nch; c++) {
        const bool more = (c + 1 < nch);
        if (more) {
            const int k0 = (c + 1) * CK;
            #pragma unroll
            for (int i = 0; i < 4; i++) {
                int s = tid + i * NTHREADS;
                int row = s >> 2, cc = s & 3;
                const float* p = &X[(m0 + row) * TDIM + k0 + cc * 8];
                xv[2 * i]     = *reinterpret_cast<const float4*>(p);
                xv[2 * i + 1] = *reinterpret_cast<const float4*>(p + 4);
            }
        }

        const uint32_t bs = sb + (st ? OX1 : OX0);
        #pragma unroll
        for (int kk = 0; kk < 2; kk++) {
            const int kg = c * 2 + kk;                // global k16 index
            uint32_t ah[4][4], bh[4][2];
            #pragma unroll
            for (int i = 0; i < 4; i++) {
                int ar = rw * 64 + i * 16 + (lane & 15);
                int chunkin = ((ar & 1) << 2) | (2 * kk + (lane >> 4));
                ldsm4(ah[i], bs + xoff(ar, chunkin));
            }
            const int g = lane >> 3;
            #pragma unroll
            for (int j2 = 0; j2 < 2; j2++) {
                int br = cw * 32 + j2 * 16 + ((g >> 1) << 3) + (lane & 7);
                int wc = 2 * kg + (g & 1);
                uint32_t r[4];
                ldsm4(r, sb + OW + woff(br, wc));
                bh[2 * j2][0] = r[0]; bh[2 * j2][1] = r[1];
                bh[2 * j2 + 1][0] = r[2]; bh[2 * j2 + 1][1] = r[3];
            }
            #pragma unroll
            for (int i = 0; i < 4; i++)
                #pragma unroll
                for (int j = 0; j < 4; j++)
                    mma16816(acc[i][j], ah[i], bh[j]);
        }

        if (more) {
            char* nbuf = smem + (st ? OX0 : OX1);
            #pragma unroll
            for (int i = 0; i < 4; i++) {
                int s = tid + i * NTHREADS;
                int row = s >> 2, cc = s & 3;
                float4 a = xv[2 * i], b = xv[2 * i + 1];
                uint4 h = make_uint4(pack2(a.x, a.y), pack2(a.z, a.w),
                                     pack2(b.x, b.y), pack2(b.z, b.w));
                int chunkin = ((row & 1) << 2) | cc;
                *reinterpret_cast<uint4*>(nbuf + xoff(row, chunkin)) = h;
            }
        }
        __syncthreads();
        st ^= 1;
    }

    // ---- epilogue: bias + direct coalesced stores ----
    const int ncol0 = n0 + cw * 32 + 2 * (lane & 3);
    float2 bj[4];
    #pragma unroll
    for (int j = 0; j < 4; j++)
        bj[j] = *reinterpret_cast<const float2*>(&bias[ncol0 + j * 8]);

    const size_t mrow = m0 + rw * 64 + (lane >> 2);
    #pragma unroll
    for (int i = 0; i < 4; i++) {
        size_t r0 = mrow + i * 16, r1 = r0 + 8;
        #pragma unroll
        for (int j = 0; j < 4; j++) {
            float2 v0 = make_float2(acc[i][j][0] + bj[j].x, acc[i][j][1] + bj[j].y);
            float2 v1 = make_float2(acc[i][j][2] + bj[j].x, acc[i][j][3] + bj[j].y);
            *reinterpret_cast<float2*>(&out[r0 * TDIM + ncol0 + j * 8]) = v0;
            *reinterpret_cast<float2*>(&out[r1 * TDIM + ncol0 + j * 8]) = v1;
        }
    }
}

extern "C" void kernel_launch(void* const* d_in, const int* in_sizes, int n_in,
                              void* d_out, int out_size)
{
    const float* x = (const float*)d_in[0];
    const float* W = (const float*)d_in[1];
    const float* b = (const float*)d_in[2];
    float* out = (float*)d_out;

    prep_w<<<TDIM, TDIM>>>(W);

    cudaFuncSetAttribute(triu_v6, cudaFuncAttributeMaxDynamicSharedMemorySize, SM_TOTAL);
    const int M = in_sizes[0] / TDIM;                 // 262144
    const int nblocks = (M / BM) * (TDIM / BN);       // 8192
    triu_v6<<<nblocks, NTHREADS, SM_TOTAL>>>(x, b, out);
}

// round 7
// speedup vs baseline: 5.0084x; 1.0040x over previous
#include <cuda_runtime.h>
#include <cuda_fp16.h>
#include <cstdint>

// out[M,256] = X[M,256] * tril(W)^T + b  via single fp16 mma.sync.
// CTA tile 256x64, 8 warps (4x2), warp tile 64x32, K chunk 32, double-buffered X,
// W fully preloaded per CTA, triangular K-skip (2/4/6/8 chunks), 2 CTAs/SM.

#define TDIM 256
#define BM   256
#define BN   64
#define CK   32
#define NTHREADS 256

// smem: W[64][512B] swizzled | X stage0 16KB | X stage1 16KB
#define OW   0
#define OX0  32768
#define OX1  49152
#define SM_TOTAL 65536

__device__ __half g_Wh[TDIM * TDIM];

__global__ void prep_w(const float* __restrict__ W) {
    int n = blockIdx.x, k = threadIdx.x;
    float v = (k <= n) ? W[n * TDIM + k] : 0.0f;
    g_Wh[n * TDIM + k] = __float2half_rn(v);
}

__device__ __forceinline__ uint32_t smem_u32(const void* p) {
    uint32_t a;
    asm("{ .reg .u64 t; cvta.to.shared.u64 t, %1; cvt.u32.u64 %0, t; }" : "=r"(a) : "l"(p));
    return a;
}

// W layout: row n = 512B (256 fp16 K-cols), 16B chunk c swizzled by n&7
__device__ __forceinline__ uint32_t woff(int n, int c) {
    return (uint32_t)(n * 512 + ((c ^ (n & 7)) << 4));
}
// X layout: two 64B rows per 128B smem row; chunkin 0..7 swizzled by (row>>1)&7
__device__ __forceinline__ uint32_t xoff(int row, int chunkin) {
    return (uint32_t)((row >> 1) * 128 + ((chunkin ^ ((row >> 1) & 7)) << 4));
}

#define CP16(dst, src) \
    asm volatile("cp.async.cg.shared.global [%0], [%1], 16;" :: "r"(dst), "l"(src) : "memory")
#define CP_COMMIT() asm volatile("cp.async.commit_group;" ::: "memory")
#define CP_WAIT0()  asm volatile("cp.async.wait_group 0;" ::: "memory")

__device__ __forceinline__ void ldsm4(uint32_t (&r)[4], uint32_t a) {
    asm volatile("ldmatrix.sync.aligned.m8n8.x4.shared.b16 {%0,%1,%2,%3}, [%4];"
        : "=r"(r[0]), "=r"(r[1]), "=r"(r[2]), "=r"(r[3]) : "r"(a));
}
__device__ __forceinline__ void mma16816(float (&d)[4], const uint32_t (&a)[4],
                                         const uint32_t* b) {
    asm volatile("mma.sync.aligned.m16n8k16.row.col.f32.f16.f16.f32 "
        "{%0,%1,%2,%3}, {%4,%5,%6,%7}, {%8,%9}, {%0,%1,%2,%3};"
        : "+f"(d[0]), "+f"(d[1]), "+f"(d[2]), "+f"(d[3])
        : "r"(a[0]), "r"(a[1]), "r"(a[2]), "r"(a[3]), "r"(b[0]), "r"(b[1]));
}
__device__ __forceinline__ uint32_t pack2(float a, float b) {
    __half2 t = __halves2half2(__float2half_rn(a), __float2half_rn(b));
    return *reinterpret_cast<uint32_t*>(&t);
}

__device__ __forceinline__ void xstore(char* buf, int row, int cc, float4 a, float4 b) {
    uint4 h = make_uint4(pack2(a.x, a.y), pack2(a.z, a.w),
                         pack2(b.x, b.y), pack2(b.z, b.w));
    int chunkin = ((row & 1) << 2) | cc;
    *reinterpret_cast<uint4*>(buf + xoff(row, chunkin)) = h;
}

__global__ __launch_bounds__(NTHREADS, 2)
void triu_v7(const float* __restrict__ X, const float* __restrict__ bias,
             float* __restrict__ out)
{
    extern __shared__ char smem[];
    const uint32_t sb = smem_u32(smem);
    const int tid = threadIdx.x;
    const int wid = tid >> 5, lane = tid & 31;

    const int bid = blockIdx.x;
    const int nb = bid & 3;                           // n-block 0..3
    const size_t m0 = (size_t)(bid >> 2) * BM;
    const int n0 = nb * BN;
    const int nch = 2 * (nb + 1);                     // CK=32 chunks: 2,4,6,8

    const int rw = wid >> 1;                          // 0..3 (64 rows each)
    const int cw = wid & 1;                           // 0..1 (32 cols each)

    // per-thread X staging coords: slot s covers row=s>>2 (8 floats at col cc*8)
    const int xrow = tid >> 2, xcc = tid & 3;

    // ---- prologue: preload all needed W (64 x nch*32) via cp.async ----
    const int wchunks = 4 * nch;                      // 16B chunks per row (<=32)
    #pragma unroll
    for (int i = 0; i < 8; i++) {
        int s = tid + i * NTHREADS;                   // 0..2047
        int n = s >> 5, c = s & 31;
        if (c < wchunks)
            CP16(sb + OW + woff(n, c), &g_Wh[(n0 + n) * TDIM + c * 8]);
    }
    CP_COMMIT();

    // ---- stage X chunk 0 (all 256 rows, direct) ----
    #pragma unroll
    for (int i = 0; i < 4; i++) {
        int row = xrow + i * 64;
        const float* p = &X[(m0 + row) * TDIM + xcc * 8];
        float4 a = *reinterpret_cast<const float4*>(p);
        float4 b = *reinterpret_cast<const float4*>(p + 4);
        xstore(smem + OX0, row, xcc, a, b);
    }
    CP_WAIT0();
    __syncthreads();

    float acc[4][4][4];
    #pragma unroll
    for (int i = 0; i < 4; i++)
        #pragma unroll
        for (int j = 0; j < 4; j++)
            #pragma unroll
            for (int e = 0; e < 4; e++) acc[i][j][e] = 0.0f;

    float4 xv[4];                                     // prefetch: rows 0..127 only
    int st = 0;
    for (int c = 0; c < nch; c++) {
        const bool more = (c + 1 < nch);
        const int k0n = (c + 1) * CK;
        if (more) {
            #pragma unroll
            for (int i = 0; i < 2; i++) {
                int row = xrow + i * 64;
                const float* p = &X[(m0 + row) * TDIM + k0n + xcc * 8];
                xv[2 * i]     = *reinterpret_cast<const float4*>(p);
                xv[2 * i + 1] = *reinterpret_cast<const float4*>(p + 4);
            }
        }

        const uint32_t bs = sb + (st ? OX1 : OX0);
        #pragma unroll
        for (int kk = 0; kk < 2; kk++) {
            const int kg = c * 2 + kk;                // global k16 index
            uint32_t ah[4][4], bh[4][2];
            #pragma unroll
            for (int i = 0; i < 4; i++) {
                int ar = rw * 64 + i * 16 + (lane & 15);
                int chunkin = ((ar & 1) << 2) | (2 * kk + (lane >> 4));
                ldsm4(ah[i], bs + xoff(ar, chunkin));
            }
            const int g = lane >> 3;
            #pragma unroll
            for (int j2 = 0; j2 < 2; j2++) {
                int br = cw * 32 + j2 * 16 + ((g >> 1) << 3) + (lane & 7);
                int wc = 2 * kg + (g & 1);
                uint32_t r[4];
                ldsm4(r, sb + OW + woff(br, wc));
                bh[2 * j2][0] = r[0]; bh[2 * j2][1] = r[1];
                bh[2 * j2 + 1][0] = r[2]; bh[2 * j2 + 1][1] = r[3];
            }
            #pragma unroll
            for (int i = 0; i < 4; i++)
                #pragma unroll
                for (int j = 0; j < 4; j++)
                    mma16816(acc[i][j], ah[i], bh[j]);
        }

        if (more) {
            char* nbuf = smem + (st ? OX0 : OX1);
            #pragma unroll
            for (int i = 0; i < 2; i++)               // prefetched half
                xstore(nbuf, xrow + i * 64, xcc, xv[2 * i], xv[2 * i + 1]);
            #pragma unroll
            for (int i = 2; i < 4; i++) {             // late half: load+convert+store
                int row = xrow + i * 64;
                const float* p = &X[(m0 + row) * TDIM + k0n + xcc * 8];
                float4 a = *reinterpret_cast<const float4*>(p);
                float4 b = *reinterpret_cast<const float4*>(p + 4);
                xstore(nbuf, row, xcc, a, b);
            }
        }
        __syncthreads();
        st ^= 1;
    }

    // ---- epilogue: bias + direct coalesced stores ----
    const int ncol0 = n0 + cw * 32 + 2 * (lane & 3);
    float2 bj[4];
    #pragma unroll
    for (int j = 0; j < 4; j++)
        bj[j] = *reinterpret_cast<const float2*>(&bias[ncol0 + j * 8]);

    const size_t mrow = m0 + rw * 64 + (lane >> 2);
    #pragma unroll
    for (int i = 0; i < 4; i++) {
        size_t r0 = mrow + i * 16, r1 = r0 + 8;
        #pragma unroll
        for (int j = 0; j < 4; j++) {
            float2 v0 = make_float2(acc[i][j][0] + bj[j].x, acc[i][j][1] + bj[j].y);
            float2 v1 = make_float2(acc[i][j][2] + bj[j].x, acc[i][j][3] + bj[j].y);
            *reinterpret_cast<float2*>(&out[r0 * TDIM + ncol0 + j * 8]) = v0;
            *reinterpret_cast<float2*>(&out[r1 * TDIM + ncol0 + j * 8]) = v1;
        }
    }
}

extern "C" void kernel_launch(void* const* d_in, const int* in_sizes, int n_in,
                              void* d_out, int out_size)
{
    const float* x = (const float*)d_in[0];
    const float* W = (const float*)d_in[1];
    const float* b = (const float*)d_in[2];
    float* out = (float*)d_out;

    prep_w<<<TDIM, TDIM>>>(W);

    cudaFuncSetAttribute(triu_v7, cudaFuncAttributeMaxDynamicSharedMemorySize, SM_TOTAL);
    const int M = in_sizes[0] / TDIM;                 // 262144
    const int nblocks = (M / BM) * (TDIM / BN);       // 4096
    triu_v7<<<nblocks, NTHREADS, SM_TOTAL>>>(x, b, out);
}